// round 3
// baseline (speedup 1.0000x reference)
#include <cuda_runtime.h>

// ---------------------------------------------------------------------------
// Problem constants
// ---------------------------------------------------------------------------
#define EMBED   1024
#define NHEADS  16
#define HDIM    64
#define NBATCH  2
#define SEQ     2048
#define TOKENS  (NBATCH * SEQ)          // 4096
#define WELEMS  (EMBED * EMBED)         // 1048576
#define SCALE_ATTN 0.125f               // 1/sqrt(64)

// ---------------------------------------------------------------------------
// Scratch (static __device__ globals; no runtime allocation allowed)
// ---------------------------------------------------------------------------
__device__ float g_Wdq[4 * WELEMS];                                  // 16 MB
__device__ int   g_absmax[4];
__device__ float g_Q[(size_t)NBATCH * NHEADS * SEQ * HDIM];          // 16 MB  [B,H,S,D]
__device__ float g_K[(size_t)NBATCH * NHEADS * SEQ * HDIM];
__device__ float g_V[(size_t)NBATCH * NHEADS * SEQ * HDIM];
__device__ float g_scores[(size_t)NBATCH * NHEADS * SEQ * SEQ];      // 512 MB [BH,S,S]
__device__ float g_ctx[(size_t)TOKENS * EMBED];                      // 16 MB  [B,S,E]

// ---------------------------------------------------------------------------
// Weight quantization (bit-faithful to reference: s = max|W|/127,
// round-half-even, clip [-128,127], dequantize)
// ---------------------------------------------------------------------------
__global__ void k_reset()
{
    if (threadIdx.x < 4) g_absmax[threadIdx.x] = 0;
}

__global__ void k_absmax(const float* __restrict__ w0, const float* __restrict__ w1,
                         const float* __restrict__ w2, const float* __restrict__ w3)
{
    const float* W = (blockIdx.y == 0) ? w0 : (blockIdx.y == 1) ? w1
                   : (blockIdx.y == 2) ? w2 : w3;
    float m = 0.0f;
    for (int i = blockIdx.x * blockDim.x + threadIdx.x; i < WELEMS;
         i += gridDim.x * blockDim.x)
        m = fmaxf(m, fabsf(W[i]));
    #pragma unroll
    for (int o = 16; o; o >>= 1)
        m = fmaxf(m, __shfl_xor_sync(0xffffffffu, m, o));
    if ((threadIdx.x & 31) == 0)
        atomicMax(&g_absmax[blockIdx.y], __float_as_int(m));  // valid: m >= 0
}

__global__ void k_dequant(const float* __restrict__ w0, const float* __restrict__ w1,
                          const float* __restrict__ w2, const float* __restrict__ w3)
{
    int sel = blockIdx.y;
    const float* W = (sel == 0) ? w0 : (sel == 1) ? w1 : (sel == 2) ? w2 : w3;
    float s = __int_as_float(g_absmax[sel]) / 127.0f;
    int i = (blockIdx.x * blockDim.x + threadIdx.x) * 4;
    float4 w = *(const float4*)&W[i];
    float4 r;
    r.x = fminf(fmaxf(rintf(w.x / s), -128.0f), 127.0f) * s;
    r.y = fminf(fmaxf(rintf(w.y / s), -128.0f), 127.0f) * s;
    r.z = fminf(fmaxf(rintf(w.z / s), -128.0f), 127.0f) * s;
    r.w = fminf(fmaxf(rintf(w.w / s), -128.0f), 127.0f) * s;
    *(float4*)&g_Wdq[(size_t)sel * WELEMS + i] = r;
}

// ---------------------------------------------------------------------------
// Tiled NT GEMM:  C[M,N] = alpha * A[M,K] * B[N,K]^T (+ bias[n])
// Block tile 128x128, BK=16, 256 threads, 8x8 micro-tile per thread.
// PERM=1: scatter output to [B,H,S,D] (QKV projections), m=(b,s), n=(h,d).
// Batched via blockIdx.z with explicit strides. All dims are exact multiples.
// ---------------------------------------------------------------------------
template <int PERM>
__global__ __launch_bounds__(256)
void gemm_nt(const float* __restrict__ A, const float* __restrict__ B,
             const float* __restrict__ bias, float* __restrict__ C,
             int M, int N, int K, float alpha,
             long long sA, long long sB, long long sC)
{
    A += (long long)blockIdx.z * sA;
    B += (long long)blockIdx.z * sB;
    C += (long long)blockIdx.z * sC;

    __shared__ float As[16][132];   // [k][m], 132 keeps float4 alignment (528B rows)
    __shared__ float Bs[16][132];   // [k][n]

    const int tid = threadIdx.x;
    const int m0 = blockIdx.y * 128;
    const int n0 = blockIdx.x * 128;
    const int lr = tid >> 2;          // 0..63
    const int lc = (tid & 3) * 4;     // 0,4,8,12
    const int tx = tid & 15;          // n micro-tile
    const int ty = tid >> 4;          // m micro-tile

    float acc[8][8] = {};

    for (int k0 = 0; k0 < K; k0 += 16) {
        float4 a0 = *(const float4*)&A[(long long)(m0 + lr)      * K + k0 + lc];
        float4 a1 = *(const float4*)&A[(long long)(m0 + lr + 64) * K + k0 + lc];
        float4 b0 = *(const float4*)&B[(long long)(n0 + lr)      * K + k0 + lc];
        float4 b1 = *(const float4*)&B[(long long)(n0 + lr + 64) * K + k0 + lc];

        __syncthreads();   // previous iteration's smem reads complete
        As[lc + 0][lr] = a0.x;  As[lc + 1][lr] = a0.y;
        As[lc + 2][lr] = a0.z;  As[lc + 3][lr] = a0.w;
        As[lc + 0][lr + 64] = a1.x;  As[lc + 1][lr + 64] = a1.y;
        As[lc + 2][lr + 64] = a1.z;  As[lc + 3][lr + 64] = a1.w;
        Bs[lc + 0][lr] = b0.x;  Bs[lc + 1][lr] = b0.y;
        Bs[lc + 2][lr] = b0.z;  Bs[lc + 3][lr] = b0.w;
        Bs[lc + 0][lr + 64] = b1.x;  Bs[lc + 1][lr + 64] = b1.y;
        Bs[lc + 2][lr + 64] = b1.z;  Bs[lc + 3][lr + 64] = b1.w;
        __syncthreads();

        #pragma unroll
        for (int k = 0; k < 16; k++) {
            float4 pa0 = *(const float4*)&As[k][ty * 8];
            float4 pa1 = *(const float4*)&As[k][ty * 8 + 4];
            float4 pb0 = *(const float4*)&Bs[k][tx * 8];
            float4 pb1 = *(const float4*)&Bs[k][tx * 8 + 4];
            float a[8] = {pa0.x, pa0.y, pa0.z, pa0.w, pa1.x, pa1.y, pa1.z, pa1.w};
            float b[8] = {pb0.x, pb0.y, pb0.z, pb0.w, pb1.x, pb1.y, pb1.z, pb1.w};
            #pragma unroll
            for (int i = 0; i < 8; i++)
                #pragma unroll
                for (int j = 0; j < 8; j++)
                    acc[i][j] = fmaf(a[i], b[j], acc[i][j]);
        }
    }

    #pragma unroll
    for (int i = 0; i < 8; i++) {
        int m = m0 + ty * 8 + i;
        #pragma unroll
        for (int j = 0; j < 8; j++) {
            int n = n0 + tx * 8 + j;
            float v = acc[i][j] * alpha;
            if (bias) v += bias[n];
            if (PERM) {
                // m = b*SEQ + s ; n = h*HDIM + d ; out layout [B,H,S,D]
                int b = m >> 11, s = m & (SEQ - 1);
                int h = n >> 6,  d = n & (HDIM - 1);
                C[(((size_t)b * NHEADS + h) * SEQ + s) * HDIM + d] = v;
            } else {
                C[(size_t)m * N + n] = v;
            }
        }
    }
}

// ---------------------------------------------------------------------------
// Softmax over rows of g_scores (row length SEQ=2048). One block per row,
// 256 threads, 8 elements/thread held in registers; single read + write.
// ---------------------------------------------------------------------------
__global__ __launch_bounds__(256)
void k_softmax(float* __restrict__ scores)
{
    const size_t row = blockIdx.x;
    float4* p = (float4*)(scores + row * (size_t)SEQ);
    const int t = threadIdx.x;

    float4 v0 = p[2 * t];
    float4 v1 = p[2 * t + 1];

    float m = fmaxf(fmaxf(fmaxf(v0.x, v0.y), fmaxf(v0.z, v0.w)),
                    fmaxf(fmaxf(v1.x, v1.y), fmaxf(v1.z, v1.w)));

    __shared__ float red[8];
    #pragma unroll
    for (int o = 16; o; o >>= 1) m = fmaxf(m, __shfl_xor_sync(0xffffffffu, m, o));
    if ((t & 31) == 0) red[t >> 5] = m;
    __syncthreads();
    m = red[t & 7];
    #pragma unroll
    for (int o = 4; o; o >>= 1) m = fmaxf(m, __shfl_xor_sync(0xffffffffu, m, o));

    v0.x = __expf(v0.x - m); v0.y = __expf(v0.y - m);
    v0.z = __expf(v0.z - m); v0.w = __expf(v0.w - m);
    v1.x = __expf(v1.x - m); v1.y = __expf(v1.y - m);
    v1.z = __expf(v1.z - m); v1.w = __expf(v1.w - m);

    float sum = v0.x + v0.y + v0.z + v0.w + v1.x + v1.y + v1.z + v1.w;
    #pragma unroll
    for (int o = 16; o; o >>= 1) sum += __shfl_xor_sync(0xffffffffu, sum, o);
    __syncthreads();                       // red reuse
    if ((t & 31) == 0) red[t >> 5] = sum;
    __syncthreads();
    sum = red[t & 7];
    #pragma unroll
    for (int o = 4; o; o >>= 1) sum += __shfl_xor_sync(0xffffffffu, sum, o);

    float inv = 1.0f / sum;
    v0.x *= inv; v0.y *= inv; v0.z *= inv; v0.w *= inv;
    v1.x *= inv; v1.y *= inv; v1.z *= inv; v1.w *= inv;
    p[2 * t]     = v0;
    p[2 * t + 1] = v1;
}

// ---------------------------------------------------------------------------
// NN GEMM for P·V:  ctx[b,s,h*64+d] = sum_k P[bh][q,k] * V[bh][k,d]
// Block tile 128x64, BK=16, 128 threads, 8x8 micro-tile.
// ---------------------------------------------------------------------------
__global__ __launch_bounds__(128)
void gemm_nn_pv(const float* __restrict__ P, const float* __restrict__ V,
                float* __restrict__ ctx)
{
    const int bh = blockIdx.z;
    const int b = bh >> 4, h = bh & 15;
    const float* A = P + (size_t)bh * SEQ * SEQ;     // [S,S]
    const float* B = V + (size_t)bh * SEQ * HDIM;    // [S,64]

    __shared__ float As[16][132];   // [k][m]
    __shared__ float Bs[16][64];    // [k][n]

    const int tid = threadIdx.x;
    const int m0 = blockIdx.y * 128;
    const int arow = tid >> 2, acol = (tid & 3) * 4;    // 32 rows/pass x4
    const int brow = tid >> 4, bcol = (tid & 15) * 4;   // 8 rows/pass x2
    const int tx = tid & 7;    // n micro
    const int ty = tid >> 3;   // m micro (0..15)

    float acc[8][8] = {};

    for (int k0 = 0; k0 < SEQ; k0 += 16) {
        float4 a[4];
        #pragma unroll
        for (int r = 0; r < 4; r++)
            a[r] = *(const float4*)&A[(long long)(m0 + arow + 32 * r) * SEQ + k0 + acol];
        float4 vb0 = *(const float4*)&B[(long long)(k0 + brow)     * HDIM + bcol];
        float4 vb1 = *(const float4*)&B[(long long)(k0 + brow + 8) * HDIM + bcol];

        __syncthreads();
        #pragma unroll
        for (int r = 0; r < 4; r++) {
            As[acol + 0][arow + 32 * r] = a[r].x;
            As[acol + 1][arow + 32 * r] = a[r].y;
            As[acol + 2][arow + 32 * r] = a[r].z;
            As[acol + 3][arow + 32 * r] = a[r].w;
        }
        *(float4*)&Bs[brow][bcol]     = vb0;
        *(float4*)&Bs[brow + 8][bcol] = vb1;
        __syncthreads();

        #pragma unroll
        for (int k = 0; k < 16; k++) {
            float4 pa0 = *(const float4*)&As[k][ty * 8];
            float4 pa1 = *(const float4*)&As[k][ty * 8 + 4];
            float4 pb0 = *(const float4*)&Bs[k][tx * 8];
            float4 pb1 = *(const float4*)&Bs[k][tx * 8 + 4];
            float aa[8] = {pa0.x, pa0.y, pa0.z, pa0.w, pa1.x, pa1.y, pa1.z, pa1.w};
            float bb[8] = {pb0.x, pb0.y, pb0.z, pb0.w, pb1.x, pb1.y, pb1.z, pb1.w};
            #pragma unroll
            for (int i = 0; i < 8; i++)
                #pragma unroll
                for (int j = 0; j < 8; j++)
                    acc[i][j] = fmaf(aa[i], bb[j], acc[i][j]);
        }
    }

    #pragma unroll
    for (int i = 0; i < 8; i++) {
        int q = m0 + ty * 8 + i;
        #pragma unroll
        for (int j = 0; j < 8; j++) {
            int d = tx * 8 + j;
            ctx[((size_t)b * SEQ + q) * EMBED + h * HDIM + d] = acc[i][j];
        }
    }
}

// ---------------------------------------------------------------------------
// Launch
// ---------------------------------------------------------------------------
extern "C" void kernel_launch(void* const* d_in, const int* in_sizes, int n_in,
                              void* d_out, int out_size)
{
    (void)in_sizes; (void)n_in; (void)out_size;
    const float* query = (const float*)d_in[0];
    const float* key   = (const float*)d_in[1];
    const float* value = (const float*)d_in[2];
    const float* Wq = (const float*)d_in[3];  const float* bq = (const float*)d_in[4];
    const float* Wk = (const float*)d_in[5];  const float* bk = (const float*)d_in[6];
    const float* Wv = (const float*)d_in[7];  const float* bv = (const float*)d_in[8];
    const float* Wo = (const float*)d_in[9];  const float* bo = (const float*)d_in[10];
    float* out = (float*)d_out;

    float *Wdq, *Qb, *Kb, *Vb, *Sc, *Cx;
    cudaGetSymbolAddress((void**)&Wdq, g_Wdq);
    cudaGetSymbolAddress((void**)&Qb,  g_Q);
    cudaGetSymbolAddress((void**)&Kb,  g_K);
    cudaGetSymbolAddress((void**)&Vb,  g_V);
    cudaGetSymbolAddress((void**)&Sc,  g_scores);
    cudaGetSymbolAddress((void**)&Cx,  g_ctx);

    // 1) Weight quant-dequant
    k_reset<<<1, 32>>>();
    k_absmax<<<dim3(256, 4), 256>>>(Wq, Wk, Wv, Wo);
    k_dequant<<<dim3(WELEMS / (256 * 4), 4), 256>>>(Wq, Wk, Wv, Wo);

    // 2) Q/K/V projections -> [B,H,S,D]
    const long long z0 = 0;
    gemm_nt<1><<<dim3(EMBED / 128, TOKENS / 128, 1), 256>>>(
        query, Wdq + 0 * (size_t)WELEMS, bq, Qb, TOKENS, EMBED, EMBED, 1.0f, z0, z0, z0);
    gemm_nt<1><<<dim3(EMBED / 128, TOKENS / 128, 1), 256>>>(
        key,   Wdq + 1 * (size_t)WELEMS, bk, Kb, TOKENS, EMBED, EMBED, 1.0f, z0, z0, z0);
    gemm_nt<1><<<dim3(EMBED / 128, TOKENS / 128, 1), 256>>>(
        value, Wdq + 2 * (size_t)WELEMS, bv, Vb, TOKENS, EMBED, EMBED, 1.0f, z0, z0, z0);

    // 3) scores = scale * Q K^T  (batched over 32 (b,h))
    gemm_nt<0><<<dim3(SEQ / 128, SEQ / 128, NBATCH * NHEADS), 256>>>(
        Qb, Kb, nullptr, Sc, SEQ, SEQ, HDIM, SCALE_ATTN,
        (long long)SEQ * HDIM, (long long)SEQ * HDIM, (long long)SEQ * SEQ);

    // 4) softmax (in place)
    k_softmax<<<NBATCH * NHEADS * SEQ, 256>>>(Sc);

    // 5) ctx = P V  -> [B,S,E]
    gemm_nn_pv<<<dim3(1, SEQ / 128, NBATCH * NHEADS), 128>>>(Sc, Vb, Cx);

    // 6) output projection -> d_out
    gemm_nt<0><<<dim3(EMBED / 128, TOKENS / 128, 1), 256>>>(
        Cx, Wdq + 3 * (size_t)WELEMS, bo, out, TOKENS, EMBED, EMBED, 1.0f, z0, z0, z0);
}

// round 5
// speedup vs baseline: 2.7990x; 2.7990x over previous
#include <cuda_runtime.h>
#include <cstdint>

// ---------------------------------------------------------------------------
// Problem constants
// ---------------------------------------------------------------------------
#define EMBED   1024
#define NHEADS  16
#define HDIM    64
#define NBATCH  2
#define SEQ     2048
#define TOKENS  (NBATCH * SEQ)          // 4096
#define WELEMS  (EMBED * EMBED)         // 1048576
#define SCALE_ATTN 0.125f               // 1/sqrt(64)
#define SA 44                           // smem row stride (floats): conflict-free & 16B aligned

// ---------------------------------------------------------------------------
// Scratch (static __device__ globals; no runtime allocation allowed)
// ---------------------------------------------------------------------------
__device__ float g_Wdq[4 * WELEMS];                                  // tf32-rounded dequant weights
__device__ int   g_absmax[4];
__device__ float g_Xin[3 * (size_t)TOKENS * EMBED];                  // tf32-rounded inputs
__device__ float g_Q[(size_t)NBATCH * NHEADS * SEQ * HDIM];          // [B,H,S,D]
__device__ float g_K[(size_t)NBATCH * NHEADS * SEQ * HDIM];
__device__ float g_V[(size_t)NBATCH * NHEADS * SEQ * HDIM];
__device__ float g_Vt[(size_t)NBATCH * NHEADS * HDIM * SEQ];         // [B,H,D,S]
__device__ float g_scores[(size_t)NBATCH * NHEADS * SEQ * SEQ];      // 512 MB [BH,S,S]
__device__ float g_ctx[(size_t)TOKENS * EMBED];                      // [B,S,E]

// ---------------------------------------------------------------------------
// Helpers (target-portable PTX only: mma.sync sm_80+, cp.async sm_80+)
// ---------------------------------------------------------------------------
__device__ __forceinline__ uint32_t smem_u32(const void* p) {
    uint32_t a;
    asm("{ .reg .u64 t; cvta.to.shared.u64 t, %1; cvt.u32.u64 %0, t; }" : "=r"(a) : "l"(p));
    return a;
}

__device__ __forceinline__ float rna_tf32(float x) {
    float r;
    asm("cvt.rna.tf32.f32 %0, %1;" : "=f"(r) : "f"(x));
    return r;
}

__device__ __forceinline__ void cp_async16(uint32_t saddr, const void* gaddr) {
    asm volatile("cp.async.cg.shared.global [%0], [%1], 16;"
                 :: "r"(saddr), "l"(gaddr) : "memory");
}

__device__ __forceinline__ void mma_tf32(float* d, const uint32_t* a, const uint32_t* b) {
    asm volatile(
        "mma.sync.aligned.m16n8k8.row.col.f32.tf32.tf32.f32 "
        "{%0,%1,%2,%3}, {%4,%5,%6,%7}, {%8,%9}, {%0,%1,%2,%3};"
        : "+f"(d[0]), "+f"(d[1]), "+f"(d[2]), "+f"(d[3])
        : "r"(a[0]), "r"(a[1]), "r"(a[2]), "r"(a[3]), "r"(b[0]), "r"(b[1]));
}

// ---------------------------------------------------------------------------
// Weight quantization (bit-faithful: s = max|W|/127, round-half-even, clip,
// dequantize), then RNA-round to tf32 so the MMA truncation is lossless.
// ---------------------------------------------------------------------------
__global__ void k_reset() { if (threadIdx.x < 4) g_absmax[threadIdx.x] = 0; }

__global__ void k_absmax(const float* __restrict__ w0, const float* __restrict__ w1,
                         const float* __restrict__ w2, const float* __restrict__ w3)
{
    const float* W = (blockIdx.y == 0) ? w0 : (blockIdx.y == 1) ? w1
                   : (blockIdx.y == 2) ? w2 : w3;
    float m = 0.0f;
    for (int i = blockIdx.x * blockDim.x + threadIdx.x; i < WELEMS;
         i += gridDim.x * blockDim.x)
        m = fmaxf(m, fabsf(W[i]));
    #pragma unroll
    for (int o = 16; o; o >>= 1) m = fmaxf(m, __shfl_xor_sync(0xffffffffu, m, o));
    if ((threadIdx.x & 31) == 0) atomicMax(&g_absmax[blockIdx.y], __float_as_int(m));
}

__global__ void k_dequant(const float* __restrict__ w0, const float* __restrict__ w1,
                          const float* __restrict__ w2, const float* __restrict__ w3)
{
    int sel = blockIdx.y;
    const float* W = (sel == 0) ? w0 : (sel == 1) ? w1 : (sel == 2) ? w2 : w3;
    float s = __int_as_float(g_absmax[sel]) / 127.0f;
    int i = (blockIdx.x * blockDim.x + threadIdx.x) * 4;
    float4 w = *(const float4*)&W[i];
    float4 r;
    r.x = rna_tf32(fminf(fmaxf(rintf(w.x / s), -128.0f), 127.0f) * s);
    r.y = rna_tf32(fminf(fmaxf(rintf(w.y / s), -128.0f), 127.0f) * s);
    r.z = rna_tf32(fminf(fmaxf(rintf(w.z / s), -128.0f), 127.0f) * s);
    r.w = rna_tf32(fminf(fmaxf(rintf(w.w / s), -128.0f), 127.0f) * s);
    *(float4*)&g_Wdq[(size_t)sel * WELEMS + i] = r;
}

__global__ void k_cvt_in(const float* __restrict__ q, const float* __restrict__ k,
                         const float* __restrict__ v)
{
    int sel = blockIdx.y;
    const float* s = (sel == 0) ? q : (sel == 1) ? k : v;
    float* d = g_Xin + (size_t)sel * TOKENS * EMBED;
    int i = (blockIdx.x * blockDim.x + threadIdx.x) * 4;
    float4 w = *(const float4*)&s[i];
    w.x = rna_tf32(w.x); w.y = rna_tf32(w.y);
    w.z = rna_tf32(w.z); w.w = rna_tf32(w.w);
    *(float4*)&d[i] = w;
}

// ---------------------------------------------------------------------------
// Tensor-core tf32 NT GEMM via mma.sync.m16n8k8:
//   C[M, N] = alpha * A[M,K] * B[N,K]^T (+ bias)
// Both operands row-major with row stride == K (dense). CTA tile 128 x BN,
// BK=32, double-buffered cp.async. Warp tile 64x32 (4x4 of m16n8k8).
// NT threads = 32 * (2 * BN/32) : BN=128 -> 256 thr, BN=64 -> 128 thr.
// MODE 0: plain row-major out (ldc, batch cZ), alpha, optional bias
// MODE 1: QKV scatter to [B,H,S,D], +bias, RNA-rounded
// MODE 2: PV -> ctx [B,S,E] scatter (z = bh index), RNA-rounded
// ---------------------------------------------------------------------------
template <int BN, int NT, int MODE>
__global__ __launch_bounds__(NT, 2)
void gemm_mma(const float* __restrict__ A, const float* __restrict__ B,
              const float* __restrict__ bias, float* __restrict__ C,
              int K, long long aZ, long long bZ, float alpha, long long cZ, int ldc)
{
    extern __shared__ float smem[];
    constexpr int STF = (128 + BN) * SA;      // floats per stage

    const int tid  = threadIdx.x;
    const int wid  = tid >> 5, lane = tid & 31;
    const int wm   = wid & 1, wn = wid >> 1;  // warp grid: 2 x (BN/32)
    const int qid  = lane >> 2, tig = lane & 3;

    const float* gA = A + (long long)blockIdx.z * aZ + (size_t)(blockIdx.y * 128) * K;
    const float* gB = B + (long long)blockIdx.z * bZ + (size_t)(blockIdx.x * BN) * K;

    float acc[4][4][4] = {};

    auto loadStage = [&](int s, int k0) {
        float* sAp = smem + s * STF;
        float* sBp = sAp + 128 * SA;
        const int r0 = tid >> 3, c = (tid & 7) * 4;
        #pragma unroll
        for (int it = 0; it < 128 * 8 / NT; ++it) {
            const int r = r0 + it * (NT / 8);
            cp_async16(smem_u32(sAp + r * SA + c), gA + (size_t)r * K + k0 + c);
        }
        #pragma unroll
        for (int it = 0; it < BN * 8 / NT; ++it) {
            const int r = r0 + it * (NT / 8);
            cp_async16(smem_u32(sBp + r * SA + c), gB + (size_t)r * K + k0 + c);
        }
        asm volatile("cp.async.commit_group;" ::: "memory");
    };

    const int ns = K / 32;
    loadStage(0, 0);
    for (int i = 0; i < ns; ++i) {
        if (i + 1 < ns) {
            loadStage((i + 1) & 1, (i + 1) * 32);
            asm volatile("cp.async.wait_group 1;" ::: "memory");
        } else {
            asm volatile("cp.async.wait_group 0;" ::: "memory");
        }
        __syncthreads();

        const float* sAp = smem + (i & 1) * STF;
        const float* sBp = sAp + 128 * SA;
        #pragma unroll
        for (int ks = 0; ks < 4; ++ks) {
            const int k = ks * 8 + tig;
            uint32_t af[4][4], bf[4][2];
            #pragma unroll
            for (int mt = 0; mt < 4; ++mt) {
                const float* ap = sAp + (wm * 64 + mt * 16 + qid) * SA + k;
                af[mt][0] = __float_as_uint(ap[0]);
                af[mt][1] = __float_as_uint(ap[8 * SA]);
                af[mt][2] = __float_as_uint(ap[4]);
                af[mt][3] = __float_as_uint(ap[8 * SA + 4]);
            }
            #pragma unroll
            for (int nt = 0; nt < 4; ++nt) {
                const float* bp = sBp + (wn * 32 + nt * 8 + qid) * SA + k;
                bf[nt][0] = __float_as_uint(bp[0]);
                bf[nt][1] = __float_as_uint(bp[4]);
            }
            #pragma unroll
            for (int mt = 0; mt < 4; ++mt)
                #pragma unroll
                for (int nt = 0; nt < 4; ++nt)
                    mma_tf32(acc[mt][nt], af[mt], bf[nt]);
        }
        __syncthreads();
    }

    // ---- epilogue ----
    const int z = blockIdx.z;
    #pragma unroll
    for (int mt = 0; mt < 4; ++mt) {
        const int m = blockIdx.y * 128 + wm * 64 + mt * 16 + qid;
        #pragma unroll
        for (int nt = 0; nt < 4; ++nt) {
            const int n = blockIdx.x * BN + wn * 32 + nt * 8 + tig * 2;
            float c0 = acc[mt][nt][0], c1 = acc[mt][nt][1];
            float c2 = acc[mt][nt][2], c3 = acc[mt][nt][3];

            if (MODE == 0) {
                c0 *= alpha; c1 *= alpha; c2 *= alpha; c3 *= alpha;
                if (bias) {
                    const float b0 = bias[n], b1 = bias[n + 1];
                    c0 += b0; c1 += b1; c2 += b0; c3 += b1;
                }
                float* p0 = C + (long long)z * cZ + (size_t)m * ldc + n;
                float* p1 = C + (long long)z * cZ + (size_t)(m + 8) * ldc + n;
                *(float2*)p0 = make_float2(c0, c1);
                *(float2*)p1 = make_float2(c2, c3);
            } else if (MODE == 1) {
                const int b = m >> 11, s2 = m & (SEQ - 1);
                const int h = n >> 6, d = n & (HDIM - 1);
                const float b0 = bias[n], b1 = bias[n + 1];
                c0 = rna_tf32(c0 + b0); c1 = rna_tf32(c1 + b1);
                c2 = rna_tf32(c2 + b0); c3 = rna_tf32(c3 + b1);
                const size_t base = ((size_t)b * NHEADS + h) * SEQ;
                *(float2*)&C[(base + s2) * HDIM + d]     = make_float2(c0, c1);
                *(float2*)&C[(base + s2 + 8) * HDIM + d] = make_float2(c2, c3);
            } else {
                const int b = z >> 4, h = z & 15;
                c0 = rna_tf32(c0); c1 = rna_tf32(c1);
                c2 = rna_tf32(c2); c3 = rna_tf32(c3);
                *(float2*)&C[((size_t)b * SEQ + m) * EMBED + h * HDIM + n]     = make_float2(c0, c1);
                *(float2*)&C[((size_t)b * SEQ + m + 8) * EMBED + h * HDIM + n] = make_float2(c2, c3);
            }
        }
    }
}

// ---------------------------------------------------------------------------
// V transpose: [BH,S,64] -> [BH,64,S]  (so PV stays a plain NT GEMM)
// ---------------------------------------------------------------------------
__global__ void k_transpose_v(const float* __restrict__ V, float* __restrict__ Vt)
{
    __shared__ float t[32][33];
    const int bh = blockIdx.z;
    const int s0 = blockIdx.x * 32, d0 = blockIdx.y * 32;
    const float* src = V + (size_t)bh * SEQ * HDIM;
    float* dst = Vt + (size_t)bh * HDIM * SEQ;
    const int x = threadIdx.x, y = threadIdx.y;    // 32 x 8
    #pragma unroll
    for (int i = 0; i < 32; i += 8)
        t[y + i][x] = src[(size_t)(s0 + y + i) * HDIM + d0 + x];
    __syncthreads();
    #pragma unroll
    for (int i = 0; i < 32; i += 8)
        dst[(size_t)(d0 + y + i) * SEQ + s0 + x] = t[x][y + i];
}

// ---------------------------------------------------------------------------
// Softmax over rows (len 2048), in place; output RNA-rounded (feeds tf32 MMA)
// ---------------------------------------------------------------------------
__global__ __launch_bounds__(256)
void k_softmax(float* __restrict__ scores)
{
    const size_t row = blockIdx.x;
    float4* p = (float4*)(scores + row * (size_t)SEQ);
    const int t = threadIdx.x;

    float4 v0 = p[2 * t];
    float4 v1 = p[2 * t + 1];

    float m = fmaxf(fmaxf(fmaxf(v0.x, v0.y), fmaxf(v0.z, v0.w)),
                    fmaxf(fmaxf(v1.x, v1.y), fmaxf(v1.z, v1.w)));

    __shared__ float red[8];
    #pragma unroll
    for (int o = 16; o; o >>= 1) m = fmaxf(m, __shfl_xor_sync(0xffffffffu, m, o));
    if ((t & 31) == 0) red[t >> 5] = m;
    __syncthreads();
    m = red[t & 7];
    #pragma unroll
    for (int o = 4; o; o >>= 1) m = fmaxf(m, __shfl_xor_sync(0xffffffffu, m, o));

    v0.x = __expf(v0.x - m); v0.y = __expf(v0.y - m);
    v0.z = __expf(v0.z - m); v0.w = __expf(v0.w - m);
    v1.x = __expf(v1.x - m); v1.y = __expf(v1.y - m);
    v1.z = __expf(v1.z - m); v1.w = __expf(v1.w - m);

    float sum = v0.x + v0.y + v0.z + v0.w + v1.x + v1.y + v1.z + v1.w;
    #pragma unroll
    for (int o = 16; o; o >>= 1) sum += __shfl_xor_sync(0xffffffffu, sum, o);
    __syncthreads();
    if ((t & 31) == 0) red[t >> 5] = sum;
    __syncthreads();
    sum = red[t & 7];
    #pragma unroll
    for (int o = 4; o; o >>= 1) sum += __shfl_xor_sync(0xffffffffu, sum, o);

    float inv = 1.0f / sum;
    v0.x = rna_tf32(v0.x * inv); v0.y = rna_tf32(v0.y * inv);
    v0.z = rna_tf32(v0.z * inv); v0.w = rna_tf32(v0.w * inv);
    v1.x = rna_tf32(v1.x * inv); v1.y = rna_tf32(v1.y * inv);
    v1.z = rna_tf32(v1.z * inv); v1.w = rna_tf32(v1.w * inv);
    p[2 * t]     = v0;
    p[2 * t + 1] = v1;
}

// ---------------------------------------------------------------------------
// Launch
// ---------------------------------------------------------------------------
#define SMEM_128 ((128 + 128) * SA * 4 * 2)   // 90112 B
#define SMEM_64  ((128 + 64)  * SA * 4 * 2)   // 67584 B

extern "C" void kernel_launch(void* const* d_in, const int* in_sizes, int n_in,
                              void* d_out, int out_size)
{
    (void)in_sizes; (void)n_in; (void)out_size;
    const float* query = (const float*)d_in[0];
    const float* key   = (const float*)d_in[1];
    const float* value = (const float*)d_in[2];
    const float* Wq = (const float*)d_in[3];  const float* bq = (const float*)d_in[4];
    const float* Wk = (const float*)d_in[5];  const float* bk = (const float*)d_in[6];
    const float* Wv = (const float*)d_in[7];  const float* bv = (const float*)d_in[8];
    const float* Wo = (const float*)d_in[9];  const float* bo = (const float*)d_in[10];
    float* out = (float*)d_out;

    float *Wdq, *Xin, *Qb, *Kb, *Vb, *Vt, *Sc, *Cx;
    cudaGetSymbolAddress((void**)&Wdq, g_Wdq);
    cudaGetSymbolAddress((void**)&Xin, g_Xin);
    cudaGetSymbolAddress((void**)&Qb,  g_Q);
    cudaGetSymbolAddress((void**)&Kb,  g_K);
    cudaGetSymbolAddress((void**)&Vb,  g_V);
    cudaGetSymbolAddress((void**)&Vt,  g_Vt);
    cudaGetSymbolAddress((void**)&Sc,  g_scores);
    cudaGetSymbolAddress((void**)&Cx,  g_ctx);

    cudaFuncSetAttribute(gemm_mma<128, 256, 0>, cudaFuncAttributeMaxDynamicSharedMemorySize, SMEM_128);
    cudaFuncSetAttribute(gemm_mma<128, 256, 1>, cudaFuncAttributeMaxDynamicSharedMemorySize, SMEM_128);
    cudaFuncSetAttribute(gemm_mma<64, 128, 2>,  cudaFuncAttributeMaxDynamicSharedMemorySize, SMEM_64);

    // 1) weight quant-dequant (+ tf32 RNA) and input tf32 RNA copies
    k_reset<<<1, 32>>>();
    k_absmax<<<dim3(256, 4), 256>>>(Wq, Wk, Wv, Wo);
    k_dequant<<<dim3(WELEMS / (256 * 4), 4), 256>>>(Wq, Wk, Wv, Wo);
    k_cvt_in<<<dim3(TOKENS * EMBED / (256 * 4), 3), 256>>>(query, key, value);

    // 2) Q/K/V projections -> [B,H,S,D] (tf32-rounded outputs)
    gemm_mma<128, 256, 1><<<dim3(EMBED / 128, TOKENS / 128, 1), 256, SMEM_128>>>(
        Xin + 0 * (size_t)TOKENS * EMBED, Wdq + 0 * (size_t)WELEMS, bq, Qb,
        EMBED, 0, 0, 1.0f, 0, 0);
    gemm_mma<128, 256, 1><<<dim3(EMBED / 128, TOKENS / 128, 1), 256, SMEM_128>>>(
        Xin + 1 * (size_t)TOKENS * EMBED, Wdq + 1 * (size_t)WELEMS, bk, Kb,
        EMBED, 0, 0, 1.0f, 0, 0);
    gemm_mma<128, 256, 1><<<dim3(EMBED / 128, TOKENS / 128, 1), 256, SMEM_128>>>(
        Xin + 2 * (size_t)TOKENS * EMBED, Wdq + 2 * (size_t)WELEMS, bv, Vb,
        EMBED, 0, 0, 1.0f, 0, 0);

    // 3) V transpose -> [B,H,D,S]
    k_transpose_v<<<dim3(SEQ / 32, HDIM / 32, NBATCH * NHEADS), dim3(32, 8)>>>(Vb, Vt);

    // 4) scores = 0.125 * Q K^T   (batched over 32 bh)
    gemm_mma<128, 256, 0><<<dim3(SEQ / 128, SEQ / 128, NBATCH * NHEADS), 256, SMEM_128>>>(
        Qb, Kb, nullptr, Sc, HDIM,
        (long long)SEQ * HDIM, (long long)SEQ * HDIM, SCALE_ATTN,
        (long long)SEQ * SEQ, SEQ);

    // 5) softmax in place (tf32-rounded output)
    k_softmax<<<NBATCH * NHEADS * SEQ, 256>>>(Sc);

    // 6) ctx = P V  (NT against V^T) -> [B,S,E] (tf32-rounded)
    gemm_mma<64, 128, 2><<<dim3(1, SEQ / 128, NBATCH * NHEADS), 128, SMEM_64>>>(
        Sc, Vt, nullptr, Cx, SEQ,
        (long long)SEQ * SEQ, (long long)HDIM * SEQ, 1.0f, 0, 0);

    // 7) output projection -> d_out
    gemm_mma<128, 256, 0><<<dim3(EMBED / 128, TOKENS / 128, 1), 256, SMEM_128>>>(
        Cx, Wdq + 3 * (size_t)WELEMS, bo, out, EMBED, 0, 0, 1.0f, 0, EMBED);
}

// round 6
// speedup vs baseline: 3.3855x; 1.2096x over previous
#include <cuda_runtime.h>
#include <cstdint>

// ---------------------------------------------------------------------------
// Problem constants
// ---------------------------------------------------------------------------
#define EMBED   1024
#define NHEADS  16
#define HDIM    64
#define NBATCH  2
#define SEQ     2048
#define TOKENS  (NBATCH * SEQ)          // 4096
#define WELEMS  (EMBED * EMBED)         // 1048576
#define SCALE_ATTN 0.125f               // 1/sqrt(64)
#define SA 44                           // GEMM smem row stride (floats)

// Flash-attention tiling
#define BQ   128
#define BKV  64
#define NJ   (SEQ / BKV)                // 32
#define SQ8  68                         // flash smem row stride (64 + 4)

// ---------------------------------------------------------------------------
// Scratch (static __device__ globals; no runtime allocation allowed)
// ---------------------------------------------------------------------------
__device__ float g_Wdq[4 * WELEMS];                                  // tf32-rounded dequant weights
__device__ int   g_absmax[4];
__device__ float g_Xin[3 * (size_t)TOKENS * EMBED];                  // tf32-rounded inputs
__device__ float g_Q[(size_t)NBATCH * NHEADS * SEQ * HDIM];          // [B,H,S,D]
__device__ float g_K[(size_t)NBATCH * NHEADS * SEQ * HDIM];
__device__ float g_V[(size_t)NBATCH * NHEADS * SEQ * HDIM];
__device__ float g_Vt[(size_t)NBATCH * NHEADS * HDIM * SEQ];         // [B,H,D,S]
__device__ float g_ctx[(size_t)TOKENS * EMBED];                      // [B,S,E]

// ---------------------------------------------------------------------------
// Helpers (target-portable PTX only: mma.sync sm_80+, cp.async sm_80+)
// ---------------------------------------------------------------------------
__device__ __forceinline__ uint32_t smem_u32(const void* p) {
    uint32_t a;
    asm("{ .reg .u64 t; cvta.to.shared.u64 t, %1; cvt.u32.u64 %0, t; }" : "=r"(a) : "l"(p));
    return a;
}

__device__ __forceinline__ float rna_tf32(float x) {
    float r;
    asm("cvt.rna.tf32.f32 %0, %1;" : "=f"(r) : "f"(x));
    return r;
}

__device__ __forceinline__ void cp_async16(uint32_t saddr, const void* gaddr) {
    asm volatile("cp.async.cg.shared.global [%0], [%1], 16;"
                 :: "r"(saddr), "l"(gaddr) : "memory");
}

__device__ __forceinline__ void mma_tf32(float* d, const uint32_t* a, const uint32_t* b) {
    asm volatile(
        "mma.sync.aligned.m16n8k8.row.col.f32.tf32.tf32.f32 "
        "{%0,%1,%2,%3}, {%4,%5,%6,%7}, {%8,%9}, {%0,%1,%2,%3};"
        : "+f"(d[0]), "+f"(d[1]), "+f"(d[2]), "+f"(d[3])
        : "r"(a[0]), "r"(a[1]), "r"(a[2]), "r"(a[3]), "r"(b[0]), "r"(b[1]));
}

// ---------------------------------------------------------------------------
// Weight quantization (bit-faithful: s = max|W|/127, round-half-even, clip,
// dequantize), then RNA-round to tf32 so the MMA truncation is lossless.
// ---------------------------------------------------------------------------
__global__ void k_reset() { if (threadIdx.x < 4) g_absmax[threadIdx.x] = 0; }

__global__ void k_absmax(const float* __restrict__ w0, const float* __restrict__ w1,
                         const float* __restrict__ w2, const float* __restrict__ w3)
{
    const float* W = (blockIdx.y == 0) ? w0 : (blockIdx.y == 1) ? w1
                   : (blockIdx.y == 2) ? w2 : w3;
    float m = 0.0f;
    for (int i = blockIdx.x * blockDim.x + threadIdx.x; i < WELEMS;
         i += gridDim.x * blockDim.x)
        m = fmaxf(m, fabsf(W[i]));
    #pragma unroll
    for (int o = 16; o; o >>= 1) m = fmaxf(m, __shfl_xor_sync(0xffffffffu, m, o));
    if ((threadIdx.x & 31) == 0) atomicMax(&g_absmax[blockIdx.y], __float_as_int(m));
}

__global__ void k_dequant(const float* __restrict__ w0, const float* __restrict__ w1,
                          const float* __restrict__ w2, const float* __restrict__ w3)
{
    int sel = blockIdx.y;
    const float* W = (sel == 0) ? w0 : (sel == 1) ? w1 : (sel == 2) ? w2 : w3;
    float s = __int_as_float(g_absmax[sel]) / 127.0f;
    int i = (blockIdx.x * blockDim.x + threadIdx.x) * 4;
    float4 w = *(const float4*)&W[i];
    float4 r;
    r.x = rna_tf32(fminf(fmaxf(rintf(w.x / s), -128.0f), 127.0f) * s);
    r.y = rna_tf32(fminf(fmaxf(rintf(w.y / s), -128.0f), 127.0f) * s);
    r.z = rna_tf32(fminf(fmaxf(rintf(w.z / s), -128.0f), 127.0f) * s);
    r.w = rna_tf32(fminf(fmaxf(rintf(w.w / s), -128.0f), 127.0f) * s);
    *(float4*)&g_Wdq[(size_t)sel * WELEMS + i] = r;
}

__global__ void k_cvt_in(const float* __restrict__ q, const float* __restrict__ k,
                         const float* __restrict__ v)
{
    int sel = blockIdx.y;
    const float* s = (sel == 0) ? q : (sel == 1) ? k : v;
    float* d = g_Xin + (size_t)sel * TOKENS * EMBED;
    int i = (blockIdx.x * blockDim.x + threadIdx.x) * 4;
    float4 w = *(const float4*)&s[i];
    w.x = rna_tf32(w.x); w.y = rna_tf32(w.y);
    w.z = rna_tf32(w.z); w.w = rna_tf32(w.w);
    *(float4*)&d[i] = w;
}

// ---------------------------------------------------------------------------
// Tensor-core tf32 NT GEMM via mma.sync.m16n8k8 (unchanged from R4 winner):
//   C[M, N] = alpha * A[M,K] * B[N,K]^T (+ bias)
// MODE 0: plain row-major out;  MODE 1: QKV scatter to [B,H,S,D], RNA-rounded
// ---------------------------------------------------------------------------
template <int BN, int NT, int MODE>
__global__ __launch_bounds__(NT, 2)
void gemm_mma(const float* __restrict__ A, const float* __restrict__ B,
              const float* __restrict__ bias, float* __restrict__ C,
              int K, long long aZ, long long bZ, float alpha, long long cZ, int ldc)
{
    extern __shared__ float smem[];
    constexpr int STF = (128 + BN) * SA;

    const int tid  = threadIdx.x;
    const int wid  = tid >> 5, lane = tid & 31;
    const int wm   = wid & 1, wn = wid >> 1;
    const int qid  = lane >> 2, tig = lane & 3;

    const float* gA = A + (long long)blockIdx.z * aZ + (size_t)(blockIdx.y * 128) * K;
    const float* gB = B + (long long)blockIdx.z * bZ + (size_t)(blockIdx.x * BN) * K;

    float acc[4][4][4] = {};

    auto loadStage = [&](int s, int k0) {
        float* sAp = smem + s * STF;
        float* sBp = sAp + 128 * SA;
        const int r0 = tid >> 3, c = (tid & 7) * 4;
        #pragma unroll
        for (int it = 0; it < 128 * 8 / NT; ++it) {
            const int r = r0 + it * (NT / 8);
            cp_async16(smem_u32(sAp + r * SA + c), gA + (size_t)r * K + k0 + c);
        }
        #pragma unroll
        for (int it = 0; it < BN * 8 / NT; ++it) {
            const int r = r0 + it * (NT / 8);
            cp_async16(smem_u32(sBp + r * SA + c), gB + (size_t)r * K + k0 + c);
        }
        asm volatile("cp.async.commit_group;" ::: "memory");
    };

    const int ns = K / 32;
    loadStage(0, 0);
    for (int i = 0; i < ns; ++i) {
        if (i + 1 < ns) {
            loadStage((i + 1) & 1, (i + 1) * 32);
            asm volatile("cp.async.wait_group 1;" ::: "memory");
        } else {
            asm volatile("cp.async.wait_group 0;" ::: "memory");
        }
        __syncthreads();

        const float* sAp = smem + (i & 1) * STF;
        const float* sBp = sAp + 128 * SA;
        #pragma unroll
        for (int ks = 0; ks < 4; ++ks) {
            const int k = ks * 8 + tig;
            uint32_t af[4][4], bf[4][2];
            #pragma unroll
            for (int mt = 0; mt < 4; ++mt) {
                const float* ap = sAp + (wm * 64 + mt * 16 + qid) * SA + k;
                af[mt][0] = __float_as_uint(ap[0]);
                af[mt][1] = __float_as_uint(ap[8 * SA]);
                af[mt][2] = __float_as_uint(ap[4]);
                af[mt][3] = __float_as_uint(ap[8 * SA + 4]);
            }
            #pragma unroll
            for (int nt = 0; nt < 4; ++nt) {
                const float* bp = sBp + (wn * 32 + nt * 8 + qid) * SA + k;
                bf[nt][0] = __float_as_uint(bp[0]);
                bf[nt][1] = __float_as_uint(bp[4]);
            }
            #pragma unroll
            for (int mt = 0; mt < 4; ++mt)
                #pragma unroll
                for (int nt = 0; nt < 4; ++nt)
                    mma_tf32(acc[mt][nt], af[mt], bf[nt]);
        }
        __syncthreads();
    }

    const int z = blockIdx.z;
    #pragma unroll
    for (int mt = 0; mt < 4; ++mt) {
        const int m = blockIdx.y * 128 + wm * 64 + mt * 16 + qid;
        #pragma unroll
        for (int nt = 0; nt < 4; ++nt) {
            const int n = blockIdx.x * BN + wn * 32 + nt * 8 + tig * 2;
            float c0 = acc[mt][nt][0], c1 = acc[mt][nt][1];
            float c2 = acc[mt][nt][2], c3 = acc[mt][nt][3];

            if (MODE == 0) {
                c0 *= alpha; c1 *= alpha; c2 *= alpha; c3 *= alpha;
                if (bias) {
                    const float b0 = bias[n], b1 = bias[n + 1];
                    c0 += b0; c1 += b1; c2 += b0; c3 += b1;
                }
                float* p0 = C + (long long)z * cZ + (size_t)m * ldc + n;
                float* p1 = C + (long long)z * cZ + (size_t)(m + 8) * ldc + n;
                *(float2*)p0 = make_float2(c0, c1);
                *(float2*)p1 = make_float2(c2, c3);
            } else {
                const int b = m >> 11, s2 = m & (SEQ - 1);
                const int h = n >> 6, d = n & (HDIM - 1);
                const float b0 = bias[n], b1 = bias[n + 1];
                c0 = rna_tf32(c0 + b0); c1 = rna_tf32(c1 + b1);
                c2 = rna_tf32(c2 + b0); c3 = rna_tf32(c3 + b1);
                const size_t base = ((size_t)b * NHEADS + h) * SEQ;
                *(float2*)&C[(base + s2) * HDIM + d]     = make_float2(c0, c1);
                *(float2*)&C[(base + s2 + 8) * HDIM + d] = make_float2(c2, c3);
            }
        }
    }
}

// ---------------------------------------------------------------------------
// V transpose: [BH,S,64] -> [BH,64,S]  (flash reads V^T as the NT B-operand)
// ---------------------------------------------------------------------------
__global__ void k_transpose_v(const float* __restrict__ V, float* __restrict__ Vt)
{
    __shared__ float t[32][33];
    const int bh = blockIdx.z;
    const int s0 = blockIdx.x * 32, d0 = blockIdx.y * 32;
    const float* src = V + (size_t)bh * SEQ * HDIM;
    float* dst = Vt + (size_t)bh * HDIM * SEQ;
    const int x = threadIdx.x, y = threadIdx.y;    // 32 x 8
    #pragma unroll
    for (int i = 0; i < 32; i += 8)
        t[y + i][x] = src[(size_t)(s0 + y + i) * HDIM + d0 + x];
    __syncthreads();
    #pragma unroll
    for (int i = 0; i < 32; i += 8)
        dst[(size_t)(d0 + y + i) * SEQ + s0 + x] = t[x][y + i];
}

// ---------------------------------------------------------------------------
// Fused flash attention: per CTA one (bh, 128-row Q tile).
// 8 warps; warp w owns Q rows [w*16, w*16+16) and the full KV width, so all
// softmax reductions are shuffles and the P smem staging is warp-private.
// S = Q K^T via mma (tf32), online softmax in regs, P (rna-tf32) -> smem ->
// A-operand of P·V mma against V^T tiles. O accumulated fp32, /l at the end.
// ---------------------------------------------------------------------------
__global__ __launch_bounds__(256, 1)
void k_flash(const float* __restrict__ Qg, const float* __restrict__ Kg,
             const float* __restrict__ Vtg, float* __restrict__ ctx)
{
    extern __shared__ float sm[];
    float* Qs = sm;                       // 128 x SQ8
    float* Ks = Qs + BQ * SQ8;            // 2 x 64 x SQ8   [kk][d]
    float* Vs = Ks + 2 * BKV * SQ8;       // 2 x 64 x SQ8   [d][kk]
    float* Ps = Vs + 2 * HDIM * SQ8;      // 128 x SQ8      [q][kk]

    const int tid = threadIdx.x;
    const int wid = tid >> 5, lane = tid & 31;
    const int qid = lane >> 2, tig = lane & 3;
    const int bh = blockIdx.z;
    const int b = bh >> 4, h = bh & 15;

    const float* gQ = Qg + ((size_t)bh * SEQ + blockIdx.x * BQ) * HDIM;
    const float* gK = Kg + (size_t)bh * SEQ * HDIM;
    const float* gV = Vtg + (size_t)bh * HDIM * SEQ;

    // Q tile load (group 0)
    #pragma unroll
    for (int it = 0; it < 8; ++it) {
        int lin = tid + it * 256;              // 0..2047 -> 128 rows x 16 float4
        int r = lin >> 4, c = (lin & 15) * 4;
        cp_async16(smem_u32(Qs + r * SQ8 + c), gQ + (size_t)r * HDIM + c);
    }
    asm volatile("cp.async.commit_group;" ::: "memory");

    auto loadKV = [&](int j, int buf) {
        float* kd = Ks + buf * BKV * SQ8;
        float* vd = Vs + buf * HDIM * SQ8;
        #pragma unroll
        for (int it = 0; it < 4; ++it) {
            int lin = tid + it * 256;          // 0..1023 -> 64 rows x 16 float4
            int r = lin >> 4, c = (lin & 15) * 4;
            cp_async16(smem_u32(kd + r * SQ8 + c), gK + (size_t)(j * BKV + r) * HDIM + c);
            cp_async16(smem_u32(vd + r * SQ8 + c), gV + (size_t)r * SEQ + j * BKV + c);
        }
        asm volatile("cp.async.commit_group;" ::: "memory");
    };

    loadKV(0, 0);

    float mrow0 = -1e30f, mrow1 = -1e30f;
    float lrow0 = 0.0f, lrow1 = 0.0f;
    float o[8][4] = {};
    const int rq = wid * 16 + qid;             // warp-private row (and +8)

    for (int j = 0; j < NJ; ++j) {
        if (j + 1 < NJ) {
            loadKV(j + 1, (j + 1) & 1);
            asm volatile("cp.async.wait_group 1;" ::: "memory");
        } else {
            asm volatile("cp.async.wait_group 0;" ::: "memory");
        }
        __syncthreads();                       // tile j visible to all warps

        // ---- S = Q K^T  (16 rows x 64 keys per warp) ----
        float s[8][4] = {};
        const float* kb = Ks + (j & 1) * BKV * SQ8;
        #pragma unroll
        for (int ks = 0; ks < 8; ++ks) {
            const int k = ks * 8 + tig;
            uint32_t af[4];
            const float* ap = Qs + rq * SQ8 + k;
            af[0] = __float_as_uint(ap[0]);
            af[1] = __float_as_uint(ap[8 * SQ8]);
            af[2] = __float_as_uint(ap[4]);
            af[3] = __float_as_uint(ap[8 * SQ8 + 4]);
            #pragma unroll
            for (int nt = 0; nt < 8; ++nt) {
                const float* bp = kb + (nt * 8 + qid) * SQ8 + k;
                uint32_t bf[2] = {__float_as_uint(bp[0]), __float_as_uint(bp[4])};
                mma_tf32(s[nt], af, bf);
            }
        }

        // ---- online softmax (rows rq and rq+8) ----
        float mx0 = -1e30f, mx1 = -1e30f;
        #pragma unroll
        for (int nt = 0; nt < 8; ++nt) {
            s[nt][0] *= SCALE_ATTN; s[nt][1] *= SCALE_ATTN;
            s[nt][2] *= SCALE_ATTN; s[nt][3] *= SCALE_ATTN;
            mx0 = fmaxf(mx0, fmaxf(s[nt][0], s[nt][1]));
            mx1 = fmaxf(mx1, fmaxf(s[nt][2], s[nt][3]));
        }
        mx0 = fmaxf(mx0, __shfl_xor_sync(0xffffffffu, mx0, 1));
        mx0 = fmaxf(mx0, __shfl_xor_sync(0xffffffffu, mx0, 2));
        mx1 = fmaxf(mx1, __shfl_xor_sync(0xffffffffu, mx1, 1));
        mx1 = fmaxf(mx1, __shfl_xor_sync(0xffffffffu, mx1, 2));
        const float mn0 = fmaxf(mrow0, mx0), mn1 = fmaxf(mrow1, mx1);
        const float a0 = __expf(mrow0 - mn0), a1 = __expf(mrow1 - mn1);
        mrow0 = mn0; mrow1 = mn1;

        float sum0 = 0.0f, sum1 = 0.0f;
        #pragma unroll
        for (int nt = 0; nt < 8; ++nt) {
            const float p0 = __expf(s[nt][0] - mn0), p1 = __expf(s[nt][1] - mn0);
            const float p2 = __expf(s[nt][2] - mn1), p3 = __expf(s[nt][3] - mn1);
            sum0 += p0 + p1; sum1 += p2 + p3;
            const int c = nt * 8 + tig * 2;
            *(float2*)&Ps[rq * SQ8 + c]       = make_float2(rna_tf32(p0), rna_tf32(p1));
            *(float2*)&Ps[(rq + 8) * SQ8 + c] = make_float2(rna_tf32(p2), rna_tf32(p3));
        }
        sum0 += __shfl_xor_sync(0xffffffffu, sum0, 1);
        sum0 += __shfl_xor_sync(0xffffffffu, sum0, 2);
        sum1 += __shfl_xor_sync(0xffffffffu, sum1, 1);
        sum1 += __shfl_xor_sync(0xffffffffu, sum1, 2);
        lrow0 = lrow0 * a0 + sum0;
        lrow1 = lrow1 * a1 + sum1;
        #pragma unroll
        for (int nt = 0; nt < 8; ++nt) {
            o[nt][0] *= a0; o[nt][1] *= a0;
            o[nt][2] *= a1; o[nt][3] *= a1;
        }
        __syncwarp();                          // Ps rows are warp-private

        // ---- O += P V   (A = Ps rows, B = V^T tile [d][kk]) ----
        const float* vb = Vs + (j & 1) * HDIM * SQ8;
        #pragma unroll
        for (int ks = 0; ks < 8; ++ks) {
            const int k = ks * 8 + tig;
            uint32_t af[4];
            const float* ap = Ps + rq * SQ8 + k;
            af[0] = __float_as_uint(ap[0]);
            af[1] = __float_as_uint(ap[8 * SQ8]);
            af[2] = __float_as_uint(ap[4]);
            af[3] = __float_as_uint(ap[8 * SQ8 + 4]);
            #pragma unroll
            for (int nt = 0; nt < 8; ++nt) {
                const float* bp = vb + (nt * 8 + qid) * SQ8 + k;
                uint32_t bf[2] = {__float_as_uint(bp[0]), __float_as_uint(bp[4])};
                mma_tf32(o[nt], af, bf);
            }
        }
        __syncthreads();                       // all reads done before next prefetch lands
    }

    // ---- epilogue: O /= l, RNA-round (feeds out-proj tf32 mma), write ctx ----
    const float inv0 = 1.0f / lrow0, inv1 = 1.0f / lrow1;
    const int q0 = blockIdx.x * BQ + rq;
    float* dst0 = ctx + ((size_t)b * SEQ + q0) * EMBED + h * HDIM;
    float* dst1 = ctx + ((size_t)b * SEQ + q0 + 8) * EMBED + h * HDIM;
    #pragma unroll
    for (int nt = 0; nt < 8; ++nt) {
        const int d = nt * 8 + tig * 2;
        *(float2*)&dst0[d] = make_float2(rna_tf32(o[nt][0] * inv0),
                                         rna_tf32(o[nt][1] * inv0));
        *(float2*)&dst1[d] = make_float2(rna_tf32(o[nt][2] * inv1),
                                         rna_tf32(o[nt][3] * inv1));
    }
}

// ---------------------------------------------------------------------------
// Launch
// ---------------------------------------------------------------------------
#define SMEM_128   ((128 + 128) * SA * 4 * 2)          // 90112 B
#define SMEM_FLASH ((BQ + 2 * BKV + 2 * HDIM + BQ) * SQ8 * 4)   // 139264 B

extern "C" void kernel_launch(void* const* d_in, const int* in_sizes, int n_in,
                              void* d_out, int out_size)
{
    (void)in_sizes; (void)n_in; (void)out_size;
    const float* query = (const float*)d_in[0];
    const float* key   = (const float*)d_in[1];
    const float* value = (const float*)d_in[2];
    const float* Wq = (const float*)d_in[3];  const float* bq = (const float*)d_in[4];
    const float* Wk = (const float*)d_in[5];  const float* bk = (const float*)d_in[6];
    const float* Wv = (const float*)d_in[7];  const float* bv = (const float*)d_in[8];
    const float* Wo = (const float*)d_in[9];  const float* bo = (const float*)d_in[10];
    float* out = (float*)d_out;

    float *Wdq, *Xin, *Qb, *Kb, *Vb, *Vt, *Cx;
    cudaGetSymbolAddress((void**)&Wdq, g_Wdq);
    cudaGetSymbolAddress((void**)&Xin, g_Xin);
    cudaGetSymbolAddress((void**)&Qb,  g_Q);
    cudaGetSymbolAddress((void**)&Kb,  g_K);
    cudaGetSymbolAddress((void**)&Vb,  g_V);
    cudaGetSymbolAddress((void**)&Vt,  g_Vt);
    cudaGetSymbolAddress((void**)&Cx,  g_ctx);

    cudaFuncSetAttribute(gemm_mma<128, 256, 0>, cudaFuncAttributeMaxDynamicSharedMemorySize, SMEM_128);
    cudaFuncSetAttribute(gemm_mma<128, 256, 1>, cudaFuncAttributeMaxDynamicSharedMemorySize, SMEM_128);
    cudaFuncSetAttribute(k_flash, cudaFuncAttributeMaxDynamicSharedMemorySize, SMEM_FLASH);

    // 1) weight quant-dequant (+ tf32 RNA) and input tf32 RNA copies
    k_reset<<<1, 32>>>();
    k_absmax<<<dim3(256, 4), 256>>>(Wq, Wk, Wv, Wo);
    k_dequant<<<dim3(WELEMS / (256 * 4), 4), 256>>>(Wq, Wk, Wv, Wo);
    k_cvt_in<<<dim3(TOKENS * EMBED / (256 * 4), 3), 256>>>(query, key, value);

    // 2) Q/K/V projections -> [B,H,S,D] (tf32-rounded outputs)
    gemm_mma<128, 256, 1><<<dim3(EMBED / 128, TOKENS / 128, 1), 256, SMEM_128>>>(
        Xin + 0 * (size_t)TOKENS * EMBED, Wdq + 0 * (size_t)WELEMS, bq, Qb,
        EMBED, 0, 0, 1.0f, 0, 0);
    gemm_mma<128, 256, 1><<<dim3(EMBED / 128, TOKENS / 128, 1), 256, SMEM_128>>>(
        Xin + 1 * (size_t)TOKENS * EMBED, Wdq + 1 * (size_t)WELEMS, bk, Kb,
        EMBED, 0, 0, 1.0f, 0, 0);
    gemm_mma<128, 256, 1><<<dim3(EMBED / 128, TOKENS / 128, 1), 256, SMEM_128>>>(
        Xin + 2 * (size_t)TOKENS * EMBED, Wdq + 2 * (size_t)WELEMS, bv, Vb,
        EMBED, 0, 0, 1.0f, 0, 0);

    // 3) V transpose -> [B,H,D,S]
    k_transpose_v<<<dim3(SEQ / 32, HDIM / 32, NBATCH * NHEADS), dim3(32, 8)>>>(Vb, Vt);

    // 4) fused attention (QK^T + online softmax + PV) -> ctx [B,S,E]
    k_flash<<<dim3(SEQ / BQ, 1, NBATCH * NHEADS), 256, SMEM_FLASH>>>(Qb, Kb, Vt, Cx);

    // 5) output projection -> d_out
    gemm_mma<128, 256, 0><<<dim3(EMBED / 128, TOKENS / 128, 1), 256, SMEM_128>>>(
        Cx, Wdq + 3 * (size_t)WELEMS, bo, out, EMBED, 0, 0, 1.0f, 0, EMBED);
}

// round 7
// speedup vs baseline: 3.7081x; 1.0953x over previous
#include <cuda_runtime.h>
#include <cstdint>

// ---------------------------------------------------------------------------
// Problem constants
// ---------------------------------------------------------------------------
#define EMBED   1024
#define NHEADS  16
#define HDIM    64
#define NBATCH  2
#define SEQ     2048
#define TOKENS  (NBATCH * SEQ)          // 4096
#define WELEMS  (EMBED * EMBED)         // 1048576
#define SCALE_ATTN 0.125f               // 1/sqrt(64)
#define SA 44                           // GEMM smem row stride (floats)

// Flash-attention tiling
#define BQ   128
#define BKV  64
#define NJ   (SEQ / BKV)                // 32
#define SQ8  68                         // flash smem row stride (64 + 4)

// ---------------------------------------------------------------------------
// Scratch (static __device__ globals; no runtime allocation allowed)
// ---------------------------------------------------------------------------
__device__ float g_Wdq[4 * WELEMS];                                  // tf32-rounded dequant weights
__device__ int   g_absmax[4];
__device__ float g_Xin[3 * (size_t)TOKENS * EMBED];                  // tf32-rounded inputs
__device__ float g_Q[(size_t)NBATCH * NHEADS * SEQ * HDIM];          // [B,H,S,D]
__device__ float g_K[(size_t)NBATCH * NHEADS * SEQ * HDIM];
__device__ float g_V[(size_t)NBATCH * NHEADS * SEQ * HDIM];
__device__ float g_Vt[(size_t)NBATCH * NHEADS * HDIM * SEQ];         // [B,H,D,S]
__device__ float g_ctx[(size_t)TOKENS * EMBED];                      // [B,S,E]

// ---------------------------------------------------------------------------
// Helpers (target-portable PTX only: mma.sync sm_80+, cp.async sm_80+)
// ---------------------------------------------------------------------------
__device__ __forceinline__ uint32_t smem_u32(const void* p) {
    uint32_t a;
    asm("{ .reg .u64 t; cvta.to.shared.u64 t, %1; cvt.u32.u64 %0, t; }" : "=r"(a) : "l"(p));
    return a;
}

__device__ __forceinline__ float rna_tf32(float x) {
    float r;
    asm("cvt.rna.tf32.f32 %0, %1;" : "=f"(r) : "f"(x));
    return r;
}

__device__ __forceinline__ void cp_async16(uint32_t saddr, const void* gaddr) {
    asm volatile("cp.async.cg.shared.global [%0], [%1], 16;"
                 :: "r"(saddr), "l"(gaddr) : "memory");
}

__device__ __forceinline__ void mma_tf32(float* d, const uint32_t* a, const uint32_t* b) {
    asm volatile(
        "mma.sync.aligned.m16n8k8.row.col.f32.tf32.tf32.f32 "
        "{%0,%1,%2,%3}, {%4,%5,%6,%7}, {%8,%9}, {%0,%1,%2,%3};"
        : "+f"(d[0]), "+f"(d[1]), "+f"(d[2]), "+f"(d[3])
        : "r"(a[0]), "r"(a[1]), "r"(a[2]), "r"(a[3]), "r"(b[0]), "r"(b[1]));
}

// ---------------------------------------------------------------------------
// Weight quantization (bit-faithful: s = max|W|/127, round-half-even, clip,
// dequantize), then RNA-round to tf32 so the MMA truncation is lossless.
// ---------------------------------------------------------------------------
__global__ void k_reset() { if (threadIdx.x < 4) g_absmax[threadIdx.x] = 0; }

__global__ void k_absmax(const float* __restrict__ w0, const float* __restrict__ w1,
                         const float* __restrict__ w2, const float* __restrict__ w3)
{
    const float* W = (blockIdx.y == 0) ? w0 : (blockIdx.y == 1) ? w1
                   : (blockIdx.y == 2) ? w2 : w3;
    float m = 0.0f;
    for (int i = blockIdx.x * blockDim.x + threadIdx.x; i < WELEMS;
         i += gridDim.x * blockDim.x)
        m = fmaxf(m, fabsf(W[i]));
    #pragma unroll
    for (int o = 16; o; o >>= 1) m = fmaxf(m, __shfl_xor_sync(0xffffffffu, m, o));
    if ((threadIdx.x & 31) == 0) atomicMax(&g_absmax[blockIdx.y], __float_as_int(m));
}

__global__ void k_dequant(const float* __restrict__ w0, const float* __restrict__ w1,
                          const float* __restrict__ w2, const float* __restrict__ w3)
{
    int sel = blockIdx.y;
    const float* W = (sel == 0) ? w0 : (sel == 1) ? w1 : (sel == 2) ? w2 : w3;
    float s = __int_as_float(g_absmax[sel]) / 127.0f;
    int i = (blockIdx.x * blockDim.x + threadIdx.x) * 4;
    float4 w = *(const float4*)&W[i];
    float4 r;
    r.x = rna_tf32(fminf(fmaxf(rintf(w.x / s), -128.0f), 127.0f) * s);
    r.y = rna_tf32(fminf(fmaxf(rintf(w.y / s), -128.0f), 127.0f) * s);
    r.z = rna_tf32(fminf(fmaxf(rintf(w.z / s), -128.0f), 127.0f) * s);
    r.w = rna_tf32(fminf(fmaxf(rintf(w.w / s), -128.0f), 127.0f) * s);
    *(float4*)&g_Wdq[(size_t)sel * WELEMS + i] = r;
}

__global__ void k_cvt_in(const float* __restrict__ q, const float* __restrict__ k,
                         const float* __restrict__ v)
{
    int sel = blockIdx.y;
    const float* s = (sel == 0) ? q : (sel == 1) ? k : v;
    float* d = g_Xin + (size_t)sel * TOKENS * EMBED;
    int i = (blockIdx.x * blockDim.x + threadIdx.x) * 4;
    float4 w = *(const float4*)&s[i];
    w.x = rna_tf32(w.x); w.y = rna_tf32(w.y);
    w.z = rna_tf32(w.z); w.w = rna_tf32(w.w);
    *(float4*)&d[i] = w;
}

// ---------------------------------------------------------------------------
// Tensor-core tf32 NT GEMM via mma.sync.m16n8k8 (unchanged — proven):
//   C[M, N] = alpha * A[M,K] * B[N,K]^T (+ bias)
// MODE 0: plain row-major out;  MODE 1: QKV scatter to [B,H,S,D], RNA-rounded
// ---------------------------------------------------------------------------
template <int BN, int NT, int MODE>
__global__ __launch_bounds__(NT, 2)
void gemm_mma(const float* __restrict__ A, const float* __restrict__ B,
              const float* __restrict__ bias, float* __restrict__ C,
              int K, long long aZ, long long bZ, float alpha, long long cZ, int ldc)
{
    extern __shared__ float smem[];
    constexpr int STF = (128 + BN) * SA;

    const int tid  = threadIdx.x;
    const int wid  = tid >> 5, lane = tid & 31;
    const int wm   = wid & 1, wn = wid >> 1;
    const int qid  = lane >> 2, tig = lane & 3;

    const float* gA = A + (long long)blockIdx.z * aZ + (size_t)(blockIdx.y * 128) * K;
    const float* gB = B + (long long)blockIdx.z * bZ + (size_t)(blockIdx.x * BN) * K;

    float acc[4][4][4] = {};

    auto loadStage = [&](int s, int k0) {
        float* sAp = smem + s * STF;
        float* sBp = sAp + 128 * SA;
        const int r0 = tid >> 3, c = (tid & 7) * 4;
        #pragma unroll
        for (int it = 0; it < 128 * 8 / NT; ++it) {
            const int r = r0 + it * (NT / 8);
            cp_async16(smem_u32(sAp + r * SA + c), gA + (size_t)r * K + k0 + c);
        }
        #pragma unroll
        for (int it = 0; it < BN * 8 / NT; ++it) {
            const int r = r0 + it * (NT / 8);
            cp_async16(smem_u32(sBp + r * SA + c), gB + (size_t)r * K + k0 + c);
        }
        asm volatile("cp.async.commit_group;" ::: "memory");
    };

    const int ns = K / 32;
    loadStage(0, 0);
    for (int i = 0; i < ns; ++i) {
        if (i + 1 < ns) {
            loadStage((i + 1) & 1, (i + 1) * 32);
            asm volatile("cp.async.wait_group 1;" ::: "memory");
        } else {
            asm volatile("cp.async.wait_group 0;" ::: "memory");
        }
        __syncthreads();

        const float* sAp = smem + (i & 1) * STF;
        const float* sBp = sAp + 128 * SA;
        #pragma unroll
        for (int ks = 0; ks < 4; ++ks) {
            const int k = ks * 8 + tig;
            uint32_t af[4][4], bf[4][2];
            #pragma unroll
            for (int mt = 0; mt < 4; ++mt) {
                const float* ap = sAp + (wm * 64 + mt * 16 + qid) * SA + k;
                af[mt][0] = __float_as_uint(ap[0]);
                af[mt][1] = __float_as_uint(ap[8 * SA]);
                af[mt][2] = __float_as_uint(ap[4]);
                af[mt][3] = __float_as_uint(ap[8 * SA + 4]);
            }
            #pragma unroll
            for (int nt = 0; nt < 4; ++nt) {
                const float* bp = sBp + (wn * 32 + nt * 8 + qid) * SA + k;
                bf[nt][0] = __float_as_uint(bp[0]);
                bf[nt][1] = __float_as_uint(bp[4]);
            }
            #pragma unroll
            for (int mt = 0; mt < 4; ++mt)
                #pragma unroll
                for (int nt = 0; nt < 4; ++nt)
                    mma_tf32(acc[mt][nt], af[mt], bf[nt]);
        }
        __syncthreads();
    }

    const int z = blockIdx.z;
    #pragma unroll
    for (int mt = 0; mt < 4; ++mt) {
        const int m = blockIdx.y * 128 + wm * 64 + mt * 16 + qid;
        #pragma unroll
        for (int nt = 0; nt < 4; ++nt) {
            const int n = blockIdx.x * BN + wn * 32 + nt * 8 + tig * 2;
            float c0 = acc[mt][nt][0], c1 = acc[mt][nt][1];
            float c2 = acc[mt][nt][2], c3 = acc[mt][nt][3];

            if (MODE == 0) {
                c0 *= alpha; c1 *= alpha; c2 *= alpha; c3 *= alpha;
                if (bias) {
                    const float b0 = bias[n], b1 = bias[n + 1];
                    c0 += b0; c1 += b1; c2 += b0; c3 += b1;
                }
                float* p0 = C + (long long)z * cZ + (size_t)m * ldc + n;
                float* p1 = C + (long long)z * cZ + (size_t)(m + 8) * ldc + n;
                *(float2*)p0 = make_float2(c0, c1);
                *(float2*)p1 = make_float2(c2, c3);
            } else {
                const int b = m >> 11, s2 = m & (SEQ - 1);
                const int h = n >> 6, d = n & (HDIM - 1);
                const float b0 = bias[n], b1 = bias[n + 1];
                c0 = rna_tf32(c0 + b0); c1 = rna_tf32(c1 + b1);
                c2 = rna_tf32(c2 + b0); c3 = rna_tf32(c3 + b1);
                const size_t base = ((size_t)b * NHEADS + h) * SEQ;
                *(float2*)&C[(base + s2) * HDIM + d]     = make_float2(c0, c1);
                *(float2*)&C[(base + s2 + 8) * HDIM + d] = make_float2(c2, c3);
            }
        }
    }
}

// ---------------------------------------------------------------------------
// V transpose: [BH,S,64] -> [BH,64,S]  (flash reads V^T as the NT B-operand)
// ---------------------------------------------------------------------------
__global__ void k_transpose_v(const float* __restrict__ V, float* __restrict__ Vt)
{
    __shared__ float t[32][33];
    const int bh = blockIdx.z;
    const int s0 = blockIdx.x * 32, d0 = blockIdx.y * 32;
    const float* src = V + (size_t)bh * SEQ * HDIM;
    float* dst = Vt + (size_t)bh * HDIM * SEQ;
    const int x = threadIdx.x, y = threadIdx.y;    // 32 x 8
    #pragma unroll
    for (int i = 0; i < 32; i += 8)
        t[y + i][x] = src[(size_t)(s0 + y + i) * HDIM + d0 + x];
    __syncthreads();
    #pragma unroll
    for (int i = 0; i < 32; i += 8)
        dst[(size_t)(d0 + y + i) * SEQ + s0 + x] = t[x][y + i];
}

// ---------------------------------------------------------------------------
// Fused flash attention, v2: register-resident P.
// Per CTA one (bh, 128-row Q tile); 8 warps; warp w owns Q rows [w*16, w*16+16).
// S = Q K^T via mma (C-frag in regs) -> online softmax in regs -> quad
// shuffles convert the C-frag directly into the A-frag of the P·V mma
// (no P smem round-trip). Smem = Q + double-buffered K/V only -> 104 KB
// -> 2 CTAs/SM (__launch_bounds__(256, 2), regs <= 128).
// ---------------------------------------------------------------------------
__global__ __launch_bounds__(256, 2)
void k_flash(const float* __restrict__ Qg, const float* __restrict__ Kg,
             const float* __restrict__ Vtg, float* __restrict__ ctx)
{
    extern __shared__ float sm[];
    float* Qs = sm;                       // 128 x SQ8
    float* Ks = Qs + BQ * SQ8;            // 2 x 64 x SQ8   [kk][d]
    float* Vs = Ks + 2 * BKV * SQ8;       // 2 x 64 x SQ8   [d][kk]

    const int tid = threadIdx.x;
    const int wid = tid >> 5, lane = tid & 31;
    const int qid = lane >> 2, tig = lane & 3;
    const int bh = blockIdx.z;
    const int b = bh >> 4, h = bh & 15;

    const float* gQ = Qg + ((size_t)bh * SEQ + blockIdx.x * BQ) * HDIM;
    const float* gK = Kg + (size_t)bh * SEQ * HDIM;
    const float* gV = Vtg + (size_t)bh * HDIM * SEQ;

    // Q tile load (own group)
    #pragma unroll
    for (int it = 0; it < 8; ++it) {
        int lin = tid + it * 256;              // 0..2047 -> 128 rows x 16 float4
        int r = lin >> 4, c = (lin & 15) * 4;
        cp_async16(smem_u32(Qs + r * SQ8 + c), gQ + (size_t)r * HDIM + c);
    }
    asm volatile("cp.async.commit_group;" ::: "memory");

    auto loadKV = [&](int j, int buf) {
        float* kd = Ks + buf * BKV * SQ8;
        float* vd = Vs + buf * HDIM * SQ8;
        #pragma unroll
        for (int it = 0; it < 4; ++it) {
            int lin = tid + it * 256;          // 0..1023 -> 64 rows x 16 float4
            int r = lin >> 4, c = (lin & 15) * 4;
            cp_async16(smem_u32(kd + r * SQ8 + c), gK + (size_t)(j * BKV + r) * HDIM + c);
            cp_async16(smem_u32(vd + r * SQ8 + c), gV + (size_t)r * SEQ + j * BKV + c);
        }
        asm volatile("cp.async.commit_group;" ::: "memory");
    };

    loadKV(0, 0);

    float mrow0 = -1e30f, mrow1 = -1e30f;
    float lrow0 = 0.0f, lrow1 = 0.0f;
    float o[8][4] = {};
    const int rq = wid * 16 + qid;             // warp-private row (and +8)

    // shuffle source lanes for C-frag -> A-frag permutation (quad-local)
    const int qbase = lane & ~3;
    const int srcA = qbase | (tig >> 1);       // holds cols {tig} as slot tig&1
    const int srcB = srcA + 2;                 // holds cols {tig+4}

    for (int j = 0; j < NJ; ++j) {
        if (j + 1 < NJ) {
            loadKV(j + 1, (j + 1) & 1);
            asm volatile("cp.async.wait_group 1;" ::: "memory");
        } else {
            asm volatile("cp.async.wait_group 0;" ::: "memory");
        }
        __syncthreads();                       // tile j visible to all warps

        // ---- S = Q K^T  (16 rows x 64 keys per warp) ----
        float s[8][4] = {};
        const float* kb = Ks + (j & 1) * BKV * SQ8;
        #pragma unroll
        for (int ks = 0; ks < 8; ++ks) {
            const int k = ks * 8 + tig;
            uint32_t af[4];
            const float* ap = Qs + rq * SQ8 + k;
            af[0] = __float_as_uint(ap[0]);
            af[1] = __float_as_uint(ap[8 * SQ8]);
            af[2] = __float_as_uint(ap[4]);
            af[3] = __float_as_uint(ap[8 * SQ8 + 4]);
            #pragma unroll
            for (int nt = 0; nt < 8; ++nt) {
                const float* bp = kb + (nt * 8 + qid) * SQ8 + k;
                uint32_t bf[2] = {__float_as_uint(bp[0]), __float_as_uint(bp[4])};
                mma_tf32(s[nt], af, bf);
            }
        }

        // ---- online softmax (rows rq and rq+8), P kept in s[][] ----
        float mx0 = -1e30f, mx1 = -1e30f;
        #pragma unroll
        for (int nt = 0; nt < 8; ++nt) {
            s[nt][0] *= SCALE_ATTN; s[nt][1] *= SCALE_ATTN;
            s[nt][2] *= SCALE_ATTN; s[nt][3] *= SCALE_ATTN;
            mx0 = fmaxf(mx0, fmaxf(s[nt][0], s[nt][1]));
            mx1 = fmaxf(mx1, fmaxf(s[nt][2], s[nt][3]));
        }
        mx0 = fmaxf(mx0, __shfl_xor_sync(0xffffffffu, mx0, 1));
        mx0 = fmaxf(mx0, __shfl_xor_sync(0xffffffffu, mx0, 2));
        mx1 = fmaxf(mx1, __shfl_xor_sync(0xffffffffu, mx1, 1));
        mx1 = fmaxf(mx1, __shfl_xor_sync(0xffffffffu, mx1, 2));
        const float mn0 = fmaxf(mrow0, mx0), mn1 = fmaxf(mrow1, mx1);
        const float a0 = __expf(mrow0 - mn0), a1 = __expf(mrow1 - mn1);
        mrow0 = mn0; mrow1 = mn1;

        float sum0 = 0.0f, sum1 = 0.0f;
        #pragma unroll
        for (int nt = 0; nt < 8; ++nt) {
            const float p0 = __expf(s[nt][0] - mn0), p1 = __expf(s[nt][1] - mn0);
            const float p2 = __expf(s[nt][2] - mn1), p3 = __expf(s[nt][3] - mn1);
            sum0 += p0 + p1; sum1 += p2 + p3;
            s[nt][0] = rna_tf32(p0); s[nt][1] = rna_tf32(p1);
            s[nt][2] = rna_tf32(p2); s[nt][3] = rna_tf32(p3);
        }
        sum0 += __shfl_xor_sync(0xffffffffu, sum0, 1);
        sum0 += __shfl_xor_sync(0xffffffffu, sum0, 2);
        sum1 += __shfl_xor_sync(0xffffffffu, sum1, 1);
        sum1 += __shfl_xor_sync(0xffffffffu, sum1, 2);
        lrow0 = lrow0 * a0 + sum0;
        lrow1 = lrow1 * a1 + sum1;
        #pragma unroll
        for (int nt = 0; nt < 8; ++nt) {
            o[nt][0] *= a0; o[nt][1] *= a0;
            o[nt][2] *= a1; o[nt][3] *= a1;
        }

        // ---- O += P V : C-frag (cols 2tig,2tig+1) -> A-frag (cols tig,tig+4)
        //      via quad shuffles; B = V^T tile [d][kk] from smem ----
        const float* vb = Vs + (j & 1) * HDIM * SQ8;
        #pragma unroll
        for (int kc = 0; kc < 8; ++kc) {       // k-chunk = cols kc*8..kc*8+7
            const float c0 = s[kc][0], c1 = s[kc][1];
            const float c2 = s[kc][2], c3 = s[kc][3];
            const float v00 = __shfl_sync(0xffffffffu, c0, srcA);
            const float v01 = __shfl_sync(0xffffffffu, c1, srcA);
            const float v10 = __shfl_sync(0xffffffffu, c0, srcB);
            const float v11 = __shfl_sync(0xffffffffu, c1, srcB);
            const float w00 = __shfl_sync(0xffffffffu, c2, srcA);
            const float w01 = __shfl_sync(0xffffffffu, c3, srcA);
            const float w10 = __shfl_sync(0xffffffffu, c2, srcB);
            const float w11 = __shfl_sync(0xffffffffu, c3, srcB);
            uint32_t af[4];
            af[0] = __float_as_uint((tig & 1) ? v01 : v00);   // P[rq  ][kc*8+tig]
            af[1] = __float_as_uint((tig & 1) ? w01 : w00);   // P[rq+8][kc*8+tig]
            af[2] = __float_as_uint((tig & 1) ? v11 : v10);   // P[rq  ][kc*8+tig+4]
            af[3] = __float_as_uint((tig & 1) ? w11 : w10);   // P[rq+8][kc*8+tig+4]
            const int k = kc * 8 + tig;
            #pragma unroll
            for (int nt = 0; nt < 8; ++nt) {
                const float* bp = vb + (nt * 8 + qid) * SQ8 + k;
                uint32_t bf[2] = {__float_as_uint(bp[0]), __float_as_uint(bp[4])};
                mma_tf32(o[nt], af, bf);
            }
        }
        __syncthreads();                       // all reads done before next prefetch lands
    }

    // ---- epilogue: O /= l, RNA-round (feeds out-proj tf32 mma), write ctx ----
    const float inv0 = 1.0f / lrow0, inv1 = 1.0f / lrow1;
    const int q0 = blockIdx.x * BQ + rq;
    float* dst0 = ctx + ((size_t)b * SEQ + q0) * EMBED + h * HDIM;
    float* dst1 = ctx + ((size_t)b * SEQ + q0 + 8) * EMBED + h * HDIM;
    #pragma unroll
    for (int nt = 0; nt < 8; ++nt) {
        const int d = nt * 8 + tig * 2;
        *(float2*)&dst0[d] = make_float2(rna_tf32(o[nt][0] * inv0),
                                         rna_tf32(o[nt][1] * inv0));
        *(float2*)&dst1[d] = make_float2(rna_tf32(o[nt][2] * inv1),
                                         rna_tf32(o[nt][3] * inv1));
    }
}

// ---------------------------------------------------------------------------
// Launch
// ---------------------------------------------------------------------------
#define SMEM_128   ((128 + 128) * SA * 4 * 2)              // 90112 B
#define SMEM_FLASH ((BQ + 2 * BKV + 2 * HDIM) * SQ8 * 4)   // 104448 B -> 2 CTAs/SM

extern "C" void kernel_launch(void* const* d_in, const int* in_sizes, int n_in,
                              void* d_out, int out_size)
{
    (void)in_sizes; (void)n_in; (void)out_size;
    const float* query = (const float*)d_in[0];
    const float* key   = (const float*)d_in[1];
    const float* value = (const float*)d_in[2];
    const float* Wq = (const float*)d_in[3];  const float* bq = (const float*)d_in[4];
    const float* Wk = (const float*)d_in[5];  const float* bk = (const float*)d_in[6];
    const float* Wv = (const float*)d_in[7];  const float* bv = (const float*)d_in[8];
    const float* Wo = (const float*)d_in[9];  const float* bo = (const float*)d_in[10];
    float* out = (float*)d_out;

    float *Wdq, *Xin, *Qb, *Kb, *Vb, *Vt, *Cx;
    cudaGetSymbolAddress((void**)&Wdq, g_Wdq);
    cudaGetSymbolAddress((void**)&Xin, g_Xin);
    cudaGetSymbolAddress((void**)&Qb,  g_Q);
    cudaGetSymbolAddress((void**)&Kb,  g_K);
    cudaGetSymbolAddress((void**)&Vb,  g_V);
    cudaGetSymbolAddress((void**)&Vt,  g_Vt);
    cudaGetSymbolAddress((void**)&Cx,  g_ctx);

    cudaFuncSetAttribute(gemm_mma<128, 256, 0>, cudaFuncAttributeMaxDynamicSharedMemorySize, SMEM_128);
    cudaFuncSetAttribute(gemm_mma<128, 256, 1>, cudaFuncAttributeMaxDynamicSharedMemorySize, SMEM_128);
    cudaFuncSetAttribute(k_flash, cudaFuncAttributeMaxDynamicSharedMemorySize, SMEM_FLASH);

    // 1) weight quant-dequant (+ tf32 RNA) and input tf32 RNA copies
    k_reset<<<1, 32>>>();
    k_absmax<<<dim3(256, 4), 256>>>(Wq, Wk, Wv, Wo);
    k_dequant<<<dim3(WELEMS / (256 * 4), 4), 256>>>(Wq, Wk, Wv, Wo);
    k_cvt_in<<<dim3(TOKENS * EMBED / (256 * 4), 3), 256>>>(query, key, value);

    // 2) Q/K/V projections -> [B,H,S,D] (tf32-rounded outputs)
    gemm_mma<128, 256, 1><<<dim3(EMBED / 128, TOKENS / 128, 1), 256, SMEM_128>>>(
        Xin + 0 * (size_t)TOKENS * EMBED, Wdq + 0 * (size_t)WELEMS, bq, Qb,
        EMBED, 0, 0, 1.0f, 0, 0);
    gemm_mma<128, 256, 1><<<dim3(EMBED / 128, TOKENS / 128, 1), 256, SMEM_128>>>(
        Xin + 1 * (size_t)TOKENS * EMBED, Wdq + 1 * (size_t)WELEMS, bk, Kb,
        EMBED, 0, 0, 1.0f, 0, 0);
    gemm_mma<128, 256, 1><<<dim3(EMBED / 128, TOKENS / 128, 1), 256, SMEM_128>>>(
        Xin + 2 * (size_t)TOKENS * EMBED, Wdq + 2 * (size_t)WELEMS, bv, Vb,
        EMBED, 0, 0, 1.0f, 0, 0);

    // 3) V transpose -> [B,H,D,S]
    k_transpose_v<<<dim3(SEQ / 32, HDIM / 32, NBATCH * NHEADS), dim3(32, 8)>>>(Vb, Vt);

    // 4) fused attention (QK^T + online softmax + PV) -> ctx [B,S,E]
    k_flash<<<dim3(SEQ / BQ, 1, NBATCH * NHEADS), 256, SMEM_FLASH>>>(Qb, Kb, Vt, Cx);

    // 5) output projection -> d_out
    gemm_mma<128, 256, 0><<<dim3(EMBED / 128, TOKENS / 128, 1), 256, SMEM_128>>>(
        Cx, Wdq + 3 * (size_t)WELEMS, bo, out, EMBED, 0, 0, 1.0f, 0, EMBED);
}